// round 10
// baseline (speedup 1.0000x reference)
#include <cuda_runtime.h>

// out[b, n] = sum_e c[b, n, e] * s[b, e]
//   B=32, N=8192, E=256 (fp32).  HBM-bound: 256 MB streamed once.
//
// R8 -> R9: shrink the work quantum to cut the ramp-down tail.
//   ROWS_PER_WARP 16 -> 4, grid 2048 -> 8192 (≈55 block generations per
//   SM slot, tail ~0.8us instead of ~3us). Steady-state path unchanged:
//   register weights, MLP=4 (2-row unroll x 2 LDG.128/lane), __ldcs.

static constexpr int B = 32;
static constexpr int N = 8192;              // rows per batch
static constexpr int E4 = 64;               // 256 floats = 64 float4 per row
static constexpr int WARPS_PER_BLOCK = 8;
static constexpr int THREADS = WARPS_PER_BLOCK * 32;        // 256
static constexpr int ROWS_PER_WARP = 4;
static constexpr int TOTAL_ROWS = B * N;                    // 262144
static constexpr int TOTAL_WARPS = TOTAL_ROWS / ROWS_PER_WARP;      // 65536
static constexpr int NUM_BLOCKS = TOTAL_WARPS / WARPS_PER_BLOCK;    // 8192
static constexpr int WARPS_PER_BATCH = N / ROWS_PER_WARP;           // 2048

__device__ __forceinline__ float dot8(float4 a0, float4 a1, float4 w0, float4 w1)
{
    float s = a0.x * w0.x;
    s = fmaf(a0.y, w0.y, s);
    s = fmaf(a0.z, w0.z, s);
    s = fmaf(a0.w, w0.w, s);
    s = fmaf(a1.x, w1.x, s);
    s = fmaf(a1.y, w1.y, s);
    s = fmaf(a1.z, w1.z, s);
    s = fmaf(a1.w, w1.w, s);
    return s;
}

__device__ __forceinline__ float warp_reduce(float v)
{
    #pragma unroll
    for (int off = 16; off > 0; off >>= 1)
        v += __shfl_xor_sync(0xFFFFFFFFu, v, off);
    return v;
}

__global__ __launch_bounds__(THREADS)
void css_dot_kernel(const float4* __restrict__ c,
                    const float4* __restrict__ s,
                    float* __restrict__ out)
{
    const int warp = threadIdx.x >> 5;
    const int lane = threadIdx.x & 31;
    const int gw   = blockIdx.x * WARPS_PER_BLOCK + warp;   // global warp id
    const int b    = gw / WARPS_PER_BATCH;                  // batch index
    const int row0 = gw * ROWS_PER_WARP;                    // global row (contiguous)

    // Weights for this batch held in registers for all 4 rows.
    const float4 w0 = s[(size_t)b * E4 + lane];
    const float4 w1 = s[(size_t)b * E4 + lane + 32];

    const float4* __restrict__ crow = c + (size_t)row0 * E4;

    #pragma unroll
    for (int k = 0; k < ROWS_PER_WARP; k += 2) {
        const float4* rA = crow + (size_t)k * E4;
        const float4* rB = rA + E4;

        // 4 independent 128-bit streaming loads per lane (MLP=4).
        float4 a0 = __ldcs(rA + lane);
        float4 a1 = __ldcs(rA + lane + 32);
        float4 b0 = __ldcs(rB + lane);
        float4 b1 = __ldcs(rB + lane + 32);

        float sumA = warp_reduce(dot8(a0, a1, w0, w1));
        float sumB = warp_reduce(dot8(b0, b1, w0, w1));

        if (lane == 0) {
            out[row0 + k]     = sumA;
            out[row0 + k + 1] = sumB;
        }
    }
}

extern "C" void kernel_launch(void* const* d_in, const int* in_sizes, int n_in,
                              void* d_out, int out_size)
{
    (void)in_sizes; (void)n_in; (void)out_size;
    const float4* c = (const float4*)d_in[0];
    const float4* s = (const float4*)d_in[1];
    float* out = (float*)d_out;

    css_dot_kernel<<<NUM_BLOCKS, THREADS>>>(c, s, out);
}